// round 10
// baseline (speedup 1.0000x reference)
#include <cuda_runtime.h>
#include <cstdint>

#define GAMMA   0.01f
#define NROWS   8192
#define NSV     5000
#define DIM     256
#define CCLS    10
#define NVSEG   500
#define NPAIR   45
#define RDIM    9      // C-1

#define MB      64     // x rows per block
#define SN      128    // sv cols per s-tile (4 tiles cover 500, zero-padded)
#define KSTR    130    // padded smem stride for Ks / Ash
#define TILEF   (16 * 128)   // floats per As/Bs buffer

// ---------------- scratch globals (no runtime alloc) -------------------------
__device__ float g_T[NROWS * RDIM * CCLS];   // T[n][r][c], 2.95 MB
__device__ int   g_ticket[NROWS / MB];       // zero-init; self-resetting

// ---------------- f32x2 helpers (bit-exact dual fp32 FMA) -------------------
__device__ __forceinline__ void ffma2(uint64_t& d, uint64_t a, uint64_t b) {
    asm("fma.rn.f32x2 %0, %1, %2, %0;" : "+l"(d) : "l"(a), "l"(b));
}
__device__ __forceinline__ float2 unpack2(uint64_t v) {
    float2 r;
    asm("mov.b64 {%0, %1}, %2;" : "=f"(r.x), "=f"(r.y) : "l"(v));
    return r;
}
__device__ __forceinline__ float dot4(float4 v) {
    return v.x * v.x + v.y * v.y + v.z * v.z + v.w * v.w;
}

// ---------------- single fused kernel ----------------------------------------
// Block (bx, c): rows bm..bm+63 of x, class segment c.
//   - norms of its x rows / sv rows computed inline from the staged tiles
//   - GEMM + exp + per-class contraction -> g_T
//   - last block per bm (atomic ticket) computes votes + writes output
__global__ __launch_bounds__(256, 3)
void svc_all_kernel(const float* __restrict__ X, const float* __restrict__ SV,
                    const float* __restrict__ A, const float* __restrict__ Bv,
                    float* __restrict__ out, int out_size)
{
    extern __shared__ float sm[];
    float* As     = sm;                      // 2 x [16][128] x-tile, dup pairs
    float* Bs     = As + 2 * TILEF;          // 2 x [16][SN]
    float* Ks     = Bs + 2 * TILEF;          // [MB][KSTR] exp'd kernel tile
    float* Ash    = Ks + MB * KSTR;          // [RDIM][KSTR] dual-coef tile
    float* xn_sh  = Ash + RDIM * KSTR;       // [64]  x row norms
    float* svn_sh = xn_sh + MB;              // [128] sv row norms (this panel)
    __shared__ int t_rank;

    const int c   = blockIdx.y;
    const int bm  = blockIdx.x * MB;
    const int tid = threadIdx.x;
    const int tx  = tid & 15;                // col group: cols tx*8 .. tx*8+7
    const int ty  = tid >> 4;                // row group: rows ty*4 .. ty*4+3

    const int a_row  = tid >> 2, a_c4 = tid & 3;      // A: 1 float4 / thread
    const int b_row0 = tid >> 2;                      // B: 2 float4 / thread
    const int b_row1 = 64 + (tid >> 2);
    const int b_c4   = tid & 3;

    float xa_acc = 0.f;                      // x-norm partial (st==0 only)

    uint64_t tac[3];
    tac[0] = tac[1] = tac[2] = 0ull;

    for (int st = 0; st < 4; st++) {
        const int sbase = st * SN;
        float sn0_acc = 0.f, sn1_acc = 0.f;  // sv-norm partials for this panel

        // load a-tile (zero-padded beyond segment length 500)
        for (int i = tid; i < RDIM * SN; i += 256) {
            int r = i >> 7, sl = i & (SN - 1);
            int s = sbase + sl;
            Ash[r * KSTR + sl] = (s < NVSEG)
                ? A[(size_t)r * NSV + c * NVSEG + s] : 0.f;
        }

        uint64_t acc[4][4];
        #pragma unroll
        for (int i = 0; i < 4; i++)
            #pragma unroll
            for (int j = 0; j < 4; j++) acc[i][j] = 0ull;

        // hoisted, kk-invariant guards / base pointers
        const int  svr0 = c * NVSEG + sbase + b_row0;
        const int  svr1 = c * NVSEG + sbase + b_row1;
        const bool g0 = (svr0 < NSV), g1 = (svr1 < NSV);
        const float* Xp  = &X[(size_t)(bm + a_row) * DIM + a_c4 * 4];
        const float* Sp0 = g0 ? &SV[(size_t)svr0 * DIM + b_c4 * 4] : SV;
        const float* Sp1 = g1 ? &SV[(size_t)svr1 * DIM + b_c4 * 4] : SV;

        // ---- prologue: load k0=0 tile, accumulate norms, stage buf 0 ----
        float4 pa, pb0, pb1;
        {
            pa  = *reinterpret_cast<const float4*>(Xp);
            pb0 = make_float4(0.f, 0.f, 0.f, 0.f);
            pb1 = make_float4(0.f, 0.f, 0.f, 0.f);
            if (g0) pb0 = *reinterpret_cast<const float4*>(Sp0);
            if (g1) pb1 = *reinterpret_cast<const float4*>(Sp1);
            if (st == 0) xa_acc += dot4(pa);
            sn0_acc += dot4(pb0);
            sn1_acc += dot4(pb1);
        }
        {
            float* Ab = As;                  // buffer 0
            float* Bb = Bs;
            float* p = &Ab[(a_c4 * 4) * 128 + 2 * a_row];
            *reinterpret_cast<float2*>(p +   0) = make_float2(pa.x, pa.x);
            *reinterpret_cast<float2*>(p + 128) = make_float2(pa.y, pa.y);
            *reinterpret_cast<float2*>(p + 256) = make_float2(pa.z, pa.z);
            *reinterpret_cast<float2*>(p + 384) = make_float2(pa.w, pa.w);
            Bb[(b_c4 * 4 + 0) * SN + b_row0] = pb0.x;
            Bb[(b_c4 * 4 + 1) * SN + b_row0] = pb0.y;
            Bb[(b_c4 * 4 + 2) * SN + b_row0] = pb0.z;
            Bb[(b_c4 * 4 + 3) * SN + b_row0] = pb0.w;
            Bb[(b_c4 * 4 + 0) * SN + b_row1] = pb1.x;
            Bb[(b_c4 * 4 + 1) * SN + b_row1] = pb1.y;
            Bb[(b_c4 * 4 + 2) * SN + b_row1] = pb1.z;
            Bb[(b_c4 * 4 + 3) * SN + b_row1] = pb1.w;
        }
        __syncthreads();

        // ---- pipelined k-loop: 16 steps of BK=16, fully unrolled ----
        #pragma unroll
        for (int kk = 0; kk < 16; kk++) {
            const int buf = kk & 1;
            const float* Ab = As + buf * TILEF;
            const float* Bb = Bs + buf * TILEF;

            if (kk < 15) {                   // compile-time after unroll
                int k0n = (kk + 1) * 16;
                pa  = *reinterpret_cast<const float4*>(Xp + k0n);
                pb0 = make_float4(0.f, 0.f, 0.f, 0.f);
                pb1 = make_float4(0.f, 0.f, 0.f, 0.f);
                if (g0) pb0 = *reinterpret_cast<const float4*>(Sp0 + k0n);
                if (g1) pb1 = *reinterpret_cast<const float4*>(Sp1 + k0n);
                if (st == 0) xa_acc += dot4(pa);
                sn0_acc += dot4(pb0);
                sn1_acc += dot4(pb1);
            }

            #pragma unroll
            for (int k = 0; k < 16; k++) {
                const ulonglong2* pa2 =
                    reinterpret_cast<const ulonglong2*>(&Ab[k * 128 + 8 * ty]);
                const ulonglong2* pb2 =
                    reinterpret_cast<const ulonglong2*>(&Bb[k * SN + 8 * tx]);
                ulonglong2 a01 = pa2[0], a23 = pa2[1];
                ulonglong2 b01 = pb2[0], b23 = pb2[1];
                uint64_t ra[4] = {a01.x, a01.y, a23.x, a23.y};
                uint64_t rb[4] = {b01.x, b01.y, b23.x, b23.y};
                #pragma unroll
                for (int i = 0; i < 4; i++)
                    #pragma unroll
                    for (int jp = 0; jp < 4; jp++)
                        ffma2(acc[i][jp], ra[i], rb[jp]);
            }

            if (kk < 15) {
                float* Aw = As + (buf ^ 1) * TILEF;
                float* Bw = Bs + (buf ^ 1) * TILEF;
                float* p = &Aw[(a_c4 * 4) * 128 + 2 * a_row];
                *reinterpret_cast<float2*>(p +   0) = make_float2(pa.x, pa.x);
                *reinterpret_cast<float2*>(p + 128) = make_float2(pa.y, pa.y);
                *reinterpret_cast<float2*>(p + 256) = make_float2(pa.z, pa.z);
                *reinterpret_cast<float2*>(p + 384) = make_float2(pa.w, pa.w);
                Bw[(b_c4 * 4 + 0) * SN + b_row0] = pb0.x;
                Bw[(b_c4 * 4 + 1) * SN + b_row0] = pb0.y;
                Bw[(b_c4 * 4 + 2) * SN + b_row0] = pb0.z;
                Bw[(b_c4 * 4 + 3) * SN + b_row0] = pb0.w;
                Bw[(b_c4 * 4 + 0) * SN + b_row1] = pb1.x;
                Bw[(b_c4 * 4 + 1) * SN + b_row1] = pb1.y;
                Bw[(b_c4 * 4 + 2) * SN + b_row1] = pb1.z;
                Bw[(b_c4 * 4 + 3) * SN + b_row1] = pb1.w;
            }
            __syncthreads();
        }

        // ---- reduce norm partials (quad shuffle over c4) ----
        {
            float s0 = sn0_acc, s1 = sn1_acc;
            s0 += __shfl_down_sync(0xFFFFFFFFu, s0, 2, 4);
            s0 += __shfl_down_sync(0xFFFFFFFFu, s0, 1, 4);
            s1 += __shfl_down_sync(0xFFFFFFFFu, s1, 2, 4);
            s1 += __shfl_down_sync(0xFFFFFFFFu, s1, 1, 4);
            if (b_c4 == 0) {
                svn_sh[b_row0] = s0;
                svn_sh[b_row1] = s1;
            }
            if (st == 0) {
                float xv = xa_acc;
                xv += __shfl_down_sync(0xFFFFFFFFu, xv, 2, 4);
                xv += __shfl_down_sync(0xFFFFFFFFu, xv, 1, 4);
                if (a_c4 == 0) xn_sh[a_row] = xv;
            }
        }
        __syncthreads();

        // ---- epilogue: k = exp(2g*dot - g*(xn+svn)) -> Ks ----
        {
            float xn[4];
            #pragma unroll
            for (int i = 0; i < 4; i++) xn[i] = xn_sh[ty * 4 + i];
            #pragma unroll
            for (int jp = 0; jp < 4; jp++) {
                int cl  = tx * 8 + 2 * jp;
                int sg0 = c * NVSEG + sbase + cl;
                bool v0 = (sg0 < NSV), v1 = (sg0 + 1 < NSV);
                float sn0 = svn_sh[cl];
                float sn1 = svn_sh[cl + 1];
                #pragma unroll
                for (int i = 0; i < 4; i++) {
                    float2 d = unpack2(acc[i][jp]);
                    float k0v = v0 ? expf(2.f * GAMMA * d.x - GAMMA * (xn[i] + sn0)) : 0.f;
                    float k1v = v1 ? expf(2.f * GAMMA * d.y - GAMMA * (xn[i] + sn1)) : 0.f;
                    *reinterpret_cast<float2*>(&Ks[(ty * 4 + i) * KSTR + cl]) =
                        make_float2(k0v, k1v);
                }
            }
        }
        __syncthreads();

        // ---- contraction: T[n][r] += sum_s Ks[n][s] * Ash[r][s] ----
        #pragma unroll
        for (int sl = 0; sl < 3; sl++) {
            int j = tid + sl * 256;
            if (j < MB * RDIM) {
                int n = j / 9, r = j - n * 9;
                const uint64_t* kp =
                    reinterpret_cast<const uint64_t*>(&Ks[n * KSTR]);
                const uint64_t* ap =
                    reinterpret_cast<const uint64_t*>(&Ash[r * KSTR]);
                #pragma unroll 8
                for (int s2 = 0; s2 < SN / 2; s2++)
                    ffma2(tac[sl], kp[s2], ap[s2]);
            }
        }
        __syncthreads();
    }

    // ---- write T slice ----
    #pragma unroll
    for (int sl = 0; sl < 3; sl++) {
        int j = tid + sl * 256;
        if (j < MB * RDIM) {
            int n = j / 9, r = j - n * 9;
            float2 v = unpack2(tac[sl]);
            g_T[(size_t)(bm + n) * (RDIM * CCLS) + r * CCLS + c] = v.x + v.y;
        }
    }

    // ---- atomic ticket: last of the 10 class-blocks for this bm votes ----
    __threadfence();
    if (tid == 0) t_rank = atomicAdd(&g_ticket[blockIdx.x], 1);
    __syncthreads();
    if (t_rank == CCLS - 1) {
        __threadfence();   // acquire: other blocks' g_T writes now visible
        if (tid < MB) {
            int n = bm + tid;
            float T[RDIM * CCLS];
            #pragma unroll
            for (int i = 0; i < RDIM * CCLS; i++)
                T[i] = g_T[(size_t)n * (RDIM * CCLS) + i];

            int counts[CCLS];
            #pragma unroll
            for (int k = 0; k < CCLS; k++) counts[k] = 0;

            int p = 0;
            #pragma unroll
            for (int i = 0; i < CCLS; i++) {
                #pragma unroll
                for (int j = i + 1; j < CCLS; j++) {
                    float cv = T[i * CCLS + j] + T[(j - 1) * CCLS + i] + Bv[p];
                    counts[(cv > 0.f) ? i : j]++;
                    p++;
                }
            }
            int best = 0;
            #pragma unroll
            for (int cls = 1; cls < CCLS; cls++)
                if (counts[cls] > counts[best]) best = cls;

            float bestf = (float)best;
            if (n < out_size) out[n] = bestf;
            if (n + NROWS < out_size) out[n + NROWS] = bestf;
        }
        if (tid == 0) g_ticket[blockIdx.x] = 0;   // reset for next replay
    }
}

// ---------------- launch ------------------------------------------------------
#define FUSED_SMEM ((2*TILEF + 2*TILEF + MB*KSTR + RDIM*KSTR + MB + SN) \
                    * (int)sizeof(float))

extern "C" void kernel_launch(void* const* d_in, const int* in_sizes, int n_in,
                              void* d_out, int out_size) {
    // size-matched dispatch (all element counts distinct), positional fallback
    const float* x  = nullptr;   // 8192*256 = 2097152
    const float* sv = nullptr;   // 5000*256 = 1280000
    const float* a  = nullptr;   // 9*5000   = 45000
    const float* b  = nullptr;   // 45
    for (int i = 0; i < n_in; i++) {
        switch (in_sizes[i]) {
            case NROWS * DIM: x  = (const float*)d_in[i]; break;
            case NSV * DIM:   sv = (const float*)d_in[i]; break;
            case RDIM * NSV:  a  = (const float*)d_in[i]; break;
            case NPAIR:       b  = (const float*)d_in[i]; break;
            default: break;
        }
    }
    if (!x || !sv || !a || !b) {
        x = (const float*)d_in[0]; sv = (const float*)d_in[1];
        a = (const float*)d_in[2]; b  = (const float*)d_in[3];
    }
    float* out = (float*)d_out;   // output dtype: float32 (class ids as floats)

    cudaFuncSetAttribute(svc_all_kernel,
                         cudaFuncAttributeMaxDynamicSharedMemorySize, FUSED_SMEM);

    dim3 fgrid(NROWS / MB, CCLS);
    svc_all_kernel<<<fgrid, 256, FUSED_SMEM>>>(x, sv, a, b, out, out_size);
}

// round 17
// speedup vs baseline: 2.6881x; 2.6881x over previous
#include <cuda_runtime.h>
#include <cstdint>

#define GAMMA   0.01f
#define NROWS   8192
#define NSV     5000
#define DIM     256
#define CCLS    10
#define NVSEG   500
#define NPAIR   45
#define RDIM    9

#define MBR     128        // x rows per block (M tile)
#define PN      64         // sv per panel (N tile)
#define NP      8          // panels: 8*64 = 512 >= 500
#define KSTR    66         // Ks / a_sh padded float stride

// smem byte offsets
#define OFF_AH   0                   // 128 rows x 512B (bf16 hi)
#define OFF_AL   65536
#define OFF_BH   131072              // 64 rows x 512B
#define OFF_BL   163840
#define OFF_KS   131072              // Ks aliases B tiles (33792 B)
#define OFF_ASH  196608              // 9 x 66 f32
#define OFF_XN   199040              // 128 f32
#define OFF_SVN  199680              // 64 f32
#define SMEM_REQ 199940

// ---------------- global scratch (no runtime alloc) --------------------------
__device__ float    g_T[NROWS * RDIM * CCLS];
__device__ int      g_ticket[NROWS / MBR];
__device__ uint16_t g_xh[NROWS * DIM],  g_xl[NROWS * DIM];
__device__ uint16_t g_svh[NSV * DIM],   g_svl[NSV * DIM];
__device__ float    g_xn[NROWS], g_svn[NSV];

// ---------------- helpers ----------------------------------------------------
__device__ __forceinline__ uint32_t smem_u32(const void* p) {
    uint32_t a;
    asm("{ .reg .u64 t; cvta.to.shared.u64 t, %1; cvt.u32.u64 %0, t; }"
        : "=r"(a) : "l"(p));
    return a;
}
__device__ __forceinline__ uint16_t bf16h(float x) {
    uint32_t b = __float_as_uint(x);
    return (uint16_t)(((b + 0x7FFFu + ((b >> 16) & 1u)) >> 16) & 0xFFFFu);
}
__device__ __forceinline__ void bf16split(float x, uint16_t& h, uint16_t& l) {
    uint32_t b = __float_as_uint(x);
    uint32_t hb = (b + 0x7FFFu + ((b >> 16) & 1u)) & 0xFFFF0000u;
    h = (uint16_t)(hb >> 16);
    l = bf16h(x - __uint_as_float(hb));
}
__device__ __forceinline__ void ffma2(uint64_t& d, uint64_t a, uint64_t b) {
    asm("fma.rn.f32x2 %0, %1, %2, %0;" : "+l"(d) : "l"(a), "l"(b));
}
__device__ __forceinline__ float2 unpack2(uint64_t v) {
    float2 r;
    asm("mov.b64 {%0, %1}, %2;" : "=f"(r.x), "=f"(r.y) : "l"(v));
    return r;
}
__device__ __forceinline__ void ldsm4(uint32_t* r, uint32_t addr) {
    asm volatile("ldmatrix.sync.aligned.m8n8.x4.shared.b16 {%0,%1,%2,%3}, [%4];"
        : "=r"(r[0]), "=r"(r[1]), "=r"(r[2]), "=r"(r[3]) : "r"(addr));
}
__device__ __forceinline__ void mma_bf16(float* d, const uint32_t* a,
                                         uint32_t b0, uint32_t b1) {
    asm volatile(
        "mma.sync.aligned.m16n8k16.row.col.f32.bf16.bf16.f32 "
        "{%0,%1,%2,%3}, {%4,%5,%6,%7}, {%8,%9}, {%0,%1,%2,%3};"
        : "+f"(d[0]), "+f"(d[1]), "+f"(d[2]), "+f"(d[3])
        : "r"(a[0]), "r"(a[1]), "r"(a[2]), "r"(a[3]), "r"(b0), "r"(b1));
}

// ---------------- conversion kernels (fp32 -> bf16 hi/lo + norms) ------------
__global__ void conv_x_kernel(const float* __restrict__ X) {
    int row = blockIdx.x;
    float v = X[(size_t)row * DIM + threadIdx.x];
    uint16_t h, l;
    bf16split(v, h, l);
    g_xh[(size_t)row * DIM + threadIdx.x] = h;
    g_xl[(size_t)row * DIM + threadIdx.x] = l;
    float s = v * v;
    #pragma unroll
    for (int off = 16; off > 0; off >>= 1)
        s += __shfl_xor_sync(0xFFFFFFFFu, s, off);
    __shared__ float red[8];
    int wid = threadIdx.x >> 5, lid = threadIdx.x & 31;
    if (lid == 0) red[wid] = s;
    __syncthreads();
    if (threadIdx.x == 0) {
        float t = 0.f;
        #pragma unroll
        for (int w = 0; w < 8; w++) t += red[w];
        g_xn[row] = t;
    }
}
__global__ void conv_sv_kernel(const float* __restrict__ SV) {
    int row = blockIdx.x;
    float v = SV[(size_t)row * DIM + threadIdx.x];
    uint16_t h, l;
    bf16split(v, h, l);
    g_svh[(size_t)row * DIM + threadIdx.x] = h;
    g_svl[(size_t)row * DIM + threadIdx.x] = l;
    float s = v * v;
    #pragma unroll
    for (int off = 16; off > 0; off >>= 1)
        s += __shfl_xor_sync(0xFFFFFFFFu, s, off);
    __shared__ float red[8];
    int wid = threadIdx.x >> 5, lid = threadIdx.x & 31;
    if (lid == 0) red[wid] = s;
    __syncthreads();
    if (threadIdx.x == 0) {
        float t = 0.f;
        #pragma unroll
        for (int w = 0; w < 8; w++) t += red[w];
        g_svn[row] = t;
    }
}

// ---------------- hot kernel: HMMA GEMM + exp + contraction + vote -----------
__global__ __launch_bounds__(256)
void svc_mma_kernel(const float* __restrict__ A, const float* __restrict__ Bv,
                    float* __restrict__ out, int out_size)
{
    extern __shared__ char smc[];
    const uint32_t smu = smem_u32(smc);
    float* Ks     = (float*)(smc + OFF_KS);
    float* a_sh   = (float*)(smc + OFF_ASH);
    float* xn_sh  = (float*)(smc + OFF_XN);
    float* svn_sh = (float*)(smc + OFF_SVN);
    __shared__ int t_rank;

    const int c    = blockIdx.y;
    const int bm   = blockIdx.x * MBR;
    const int tid  = threadIdx.x;
    const int wid  = tid >> 5;
    const int lane = tid & 31;
    const int wy   = wid >> 1;          // 0..3 (m)
    const int wx   = wid & 1;           // 0..1 (n)
    const int g    = lane >> 2;
    const int qi   = lane & 3;
    const int t16  = lane & 15;
    const int th   = lane >> 4;
    const int row7 = t16 & 7;

    // ldmatrix row bases (byte offsets within a tile; row stride 512B)
    uint32_t rA[2], rB[2];
    #pragma unroll
    for (int mi = 0; mi < 2; mi++) rA[mi] = (uint32_t)(wy * 32 + mi * 16 + t16) * 512u;
    #pragma unroll
    for (int nj = 0; nj < 2; nj++) rB[nj] = (uint32_t)(wx * 32 + nj * 16 + t16) * 512u;
    const uint32_t AhU = smu + OFF_AH, AlU = smu + OFF_AL;
    const uint32_t BhU = smu + OFF_BH, BlU = smu + OFF_BL;

    // ---- stage Ah/Al (full K=256) ----
    #pragma unroll
    for (int it = 0; it < 16; it++) {
        int idx = tid + it * 256;
        int m = idx >> 5, ch = idx & 31;
        uint32_t off = (uint32_t)m * 512u + (uint32_t)((ch ^ (m & 7)) << 4);
        size_t src = (size_t)(bm + m) * DIM + ch * 8;
        *(uint4*)(smc + OFF_AH + off) = *(const uint4*)&g_xh[src];
        *(uint4*)(smc + OFF_AL + off) = *(const uint4*)&g_xl[src];
    }
    if (tid < MBR) xn_sh[tid] = g_xn[bm + tid];

    uint64_t tac[5];
    #pragma unroll
    for (int i = 0; i < 5; i++) tac[i] = 0ull;

    for (int p = 0; p < NP; p++) {
        __syncthreads();   // prev contraction done with Ks (aliases B tiles)

        // ---- stage Bh/Bl panel (zero-pad n >= 500) ----
        #pragma unroll
        for (int it = 0; it < 8; it++) {
            int idx = tid + it * 256;
            int n = idx >> 5, ch = idx & 31;
            int nseg = p * PN + n;
            uint32_t off = (uint32_t)n * 512u + (uint32_t)((ch ^ (n & 7)) << 4);
            uint4 vh = make_uint4(0, 0, 0, 0), vl = vh;
            if (nseg < NVSEG) {
                size_t src = (size_t)(c * NVSEG + nseg) * DIM + ch * 8;
                vh = *(const uint4*)&g_svh[src];
                vl = *(const uint4*)&g_svl[src];
            }
            *(uint4*)(smc + OFF_BH + off) = vh;
            *(uint4*)(smc + OFF_BL + off) = vl;
        }
        if (tid < PN) {
            int nseg = p * PN + tid;
            svn_sh[tid] = (nseg < NVSEG) ? g_svn[c * NVSEG + nseg] : 0.f;
        }
        for (int i = tid; i < RDIM * PN; i += 256) {
            int r = i >> 6, j = i & 63;
            int nseg = p * PN + j;
            a_sh[r * KSTR + j] = (nseg < NVSEG)
                ? A[(size_t)r * NSV + c * NVSEG + nseg] : 0.f;
        }
        __syncthreads();

        // ---- mainloop: 16 k-steps, 3-pass bf16-split mma ----
        float d[2][4][4];
        #pragma unroll
        for (int mi = 0; mi < 2; mi++)
            #pragma unroll
            for (int ni = 0; ni < 4; ni++)
                #pragma unroll
                for (int q = 0; q < 4; q++) d[mi][ni][q] = 0.f;

        #pragma unroll 4
        for (int ks = 0; ks < 16; ks++) {
            uint32_t chunk = (uint32_t)(((ks * 2 + th) ^ row7) << 4);
            uint32_t ah[2][4], al[2][4], bh[2][4], bl[2][4];
            #pragma unroll
            for (int mi = 0; mi < 2; mi++) {
                ldsm4(ah[mi], AhU + rA[mi] + chunk);
                ldsm4(al[mi], AlU + rA[mi] + chunk);
            }
            #pragma unroll
            for (int nj = 0; nj < 2; nj++) {
                ldsm4(bh[nj], BhU + rB[nj] + chunk);
                ldsm4(bl[nj], BlU + rB[nj] + chunk);
            }
            #pragma unroll
            for (int mi = 0; mi < 2; mi++)
                #pragma unroll
                for (int ni = 0; ni < 4; ni++) {
                    int nj = ni >> 1, s = ni & 1;
                    mma_bf16(d[mi][ni], ah[mi], bh[nj][s], bh[nj][s + 2]);
                    mma_bf16(d[mi][ni], ah[mi], bl[nj][s], bl[nj][s + 2]);
                    mma_bf16(d[mi][ni], al[mi], bh[nj][s], bh[nj][s + 2]);
                }
        }
        __syncthreads();   // all ldmatrix done before Ks overwrites B tiles

        // ---- epilogue: exp -> Ks ----
        #pragma unroll
        for (int mi = 0; mi < 2; mi++) {
            int row0 = wy * 32 + mi * 16 + g;
            float xn0 = xn_sh[row0], xn8 = xn_sh[row0 + 8];
            #pragma unroll
            for (int ni = 0; ni < 4; ni++) {
                int col = wx * 32 + ni * 8 + 2 * qi;
                float s0 = svn_sh[col], s1 = svn_sh[col + 1];
                float k00 = expf(2.f * GAMMA * d[mi][ni][0] - GAMMA * (xn0 + s0));
                float k01 = expf(2.f * GAMMA * d[mi][ni][1] - GAMMA * (xn0 + s1));
                float k10 = expf(2.f * GAMMA * d[mi][ni][2] - GAMMA * (xn8 + s0));
                float k11 = expf(2.f * GAMMA * d[mi][ni][3] - GAMMA * (xn8 + s1));
                *(float2*)&Ks[row0 * KSTR + col]       = make_float2(k00, k01);
                *(float2*)&Ks[(row0 + 8) * KSTR + col] = make_float2(k10, k11);
            }
        }
        __syncthreads();

        // ---- contraction: T[n][r] += sum_{64 cols} Ks[n][col] * a_sh[r][col]
        #pragma unroll
        for (int sl = 0; sl < 5; sl++) {
            int j = tid + sl * 256;
            if (j < MBR * RDIM) {
                int n = j / 9, r = j - n * 9;
                const uint64_t* kp = (const uint64_t*)&Ks[n * KSTR];
                const uint64_t* ap = (const uint64_t*)&a_sh[r * KSTR];
                #pragma unroll 8
                for (int s2 = 0; s2 < 32; s2++)
                    ffma2(tac[sl], kp[s2], ap[s2]);
            }
        }
    }

    // ---- write T ----
    #pragma unroll
    for (int sl = 0; sl < 5; sl++) {
        int j = tid + sl * 256;
        if (j < MBR * RDIM) {
            int n = j / 9, r = j - n * 9;
            float2 v = unpack2(tac[sl]);
            g_T[(size_t)(bm + n) * (RDIM * CCLS) + r * CCLS + c] = v.x + v.y;
        }
    }

    // ---- ticket: last of the 10 class-blocks for this bm votes ----
    __threadfence();
    if (tid == 0) t_rank = atomicAdd(&g_ticket[blockIdx.x], 1);
    __syncthreads();
    if (t_rank == CCLS - 1) {
        __threadfence();
        if (tid < MBR) {
            int n = bm + tid;
            float T[RDIM * CCLS];
            #pragma unroll
            for (int i = 0; i < RDIM * CCLS; i++)
                T[i] = g_T[(size_t)n * (RDIM * CCLS) + i];
            int counts[CCLS];
            #pragma unroll
            for (int k = 0; k < CCLS; k++) counts[k] = 0;
            int pp = 0;
            #pragma unroll
            for (int i = 0; i < CCLS; i++)
                #pragma unroll
                for (int j = i + 1; j < CCLS; j++) {
                    float cv = T[i * CCLS + j] + T[(j - 1) * CCLS + i] + Bv[pp];
                    counts[(cv > 0.f) ? i : j]++;
                    pp++;
                }
            int best = 0;
            #pragma unroll
            for (int cls = 1; cls < CCLS; cls++)
                if (counts[cls] > counts[best]) best = cls;
            float bestf = (float)best;
            if (n < out_size) out[n] = bestf;
            if (n + NROWS < out_size) out[n + NROWS] = bestf;
        }
        if (tid == 0) g_ticket[blockIdx.x] = 0;
    }
}

// ---------------- launch ------------------------------------------------------
extern "C" void kernel_launch(void* const* d_in, const int* in_sizes, int n_in,
                              void* d_out, int out_size) {
    const float* x  = nullptr;
    const float* sv = nullptr;
    const float* a  = nullptr;
    const float* b  = nullptr;
    for (int i = 0; i < n_in; i++) {
        switch (in_sizes[i]) {
            case NROWS * DIM: x  = (const float*)d_in[i]; break;
            case NSV * DIM:   sv = (const float*)d_in[i]; break;
            case RDIM * NSV:  a  = (const float*)d_in[i]; break;
            case NPAIR:       b  = (const float*)d_in[i]; break;
            default: break;
        }
    }
    if (!x || !sv || !a || !b) {
        x = (const float*)d_in[0]; sv = (const float*)d_in[1];
        a = (const float*)d_in[2]; b  = (const float*)d_in[3];
    }
    float* out = (float*)d_out;

    cudaFuncSetAttribute(svc_mma_kernel,
                         cudaFuncAttributeMaxDynamicSharedMemorySize, SMEM_REQ);

    conv_x_kernel<<<NROWS, 256>>>(x);
    conv_sv_kernel<<<NSV, 256>>>(sv);

    dim3 grid(NROWS / MBR, CCLS);
    svc_mma_kernel<<<grid, 256, SMEM_REQ>>>(a, b, out, out_size);
}